// round 1
// baseline (speedup 1.0000x reference)
#include <cuda_runtime.h>

#define N_TOKENS 2048   // 8 * 256
#define DIM 128
#define DC 16

__global__ void __launch_bounds__(DIM) flf_quant_kernel(
    const float* __restrict__ x,      // [2048, 128]
    const float* __restrict__ W_in,   // [128, 16]
    const float* __restrict__ b_in,   // [16]
    const float* __restrict__ W_out,  // [16, 128]
    const float* __restrict__ b_out,  // [128]
    float* __restrict__ out,          // [2048*128 (+ 2048 indices)]
    int write_indices)
{
    __shared__ float xs[DIM];
    __shared__ float partial[DIM];    // logically [8 chunks][16 dims]
    __shared__ float s[DC];           // +1 / -1 per code dim
    __shared__ int   sidx;

    const int token = blockIdx.x;
    const int t = threadIdx.x;

    // Vectorized load of this token's x row into shared (32 * float4 = 128 floats)
    if (t < 32) {
        reinterpret_cast<float4*>(xs)[t] =
            reinterpret_cast<const float4*>(x + (size_t)token * DIM)[t];
    }
    __syncthreads();

    // z = x @ W_in : each thread handles code-dim e = t&15, input chunk c = t>>4 (16 dims)
    {
        const int e = t & 15;
        const int c = t >> 4;
        float p = 0.0f;
        const float* wcol = W_in + (c * 16) * DC + e;
        #pragma unroll
        for (int i = 0; i < 16; i++) {
            p = fmaf(xs[c * 16 + i], wcol[i * DC], p);
        }
        partial[t] = p;
    }
    __syncthreads();

    // Reduce 8 partials per code dim; extract sign bits -> index (threads 0..15, warp 0)
    if (t < DC) {
        float z = b_in[t];
        #pragma unroll
        for (int c = 0; c < 8; c++) z += partial[c * 16 + t];
        const bool pos = (z > 0.0f);   // strict: tie (z==0) -> bit 0, matching argmin
        unsigned ballot = __ballot_sync(0x0000FFFFu, pos);
        s[t] = pos ? 1.0f : -1.0f;
        if (t == 0) sidx = (int)(__brev(ballot & 0xFFFFu) >> 16);
    }
    __syncthreads();

    // out = quantized @ W_out + b_out : thread t -> output dim t, coalesced W_out reads
    float o = b_out[t];
    #pragma unroll
    for (int e = 0; e < DC; e++) {
        o = fmaf(s[e], W_out[e * DIM + t], o);
    }
    out[(size_t)token * DIM + t] = o;

    if (write_indices && t == 0) {
        out[(size_t)N_TOKENS * DIM + token] = (float)sidx;
    }
}

extern "C" void kernel_launch(void* const* d_in, const int* in_sizes, int n_in,
                              void* d_out, int out_size)
{
    const float* x     = (const float*)d_in[0];
    const float* W_in  = (const float*)d_in[1];
    const float* b_in  = (const float*)d_in[2];
    const float* W_out = (const float*)d_in[3];
    const float* b_out = (const float*)d_in[4];
    float* out = (float*)d_out;

    // If the harness buffer includes the second tuple output (encoding_indices),
    // write the indices as floats after the flattened `out` tensor.
    int write_indices = (out_size >= N_TOKENS * DIM + N_TOKENS) ? 1 : 0;

    flf_quant_kernel<<<N_TOKENS, DIM>>>(x, W_in, b_in, W_out, b_out, out, write_indices);
}